// round 1
// baseline (speedup 1.0000x reference)
#include <cuda_runtime.h>
#include <math.h>

#define B   64
#define T   1000
#define RNN 1024
#define EMB 512
#define ATT 128
#define LOC 32
#define KS  31
#define TCH 8
#define TILE 125   // T / TCH

// scratch (no allocations allowed in kernel_launch)
__device__ float g_pq[B * ATT];
__device__ float g_energy[B * T];
__device__ float g_partial[B * TCH * EMB];

// ---------------------------------------------------------------------------
// Kernel 1: processed query  pq[b][a] = sum_k h[b][k] * Wq[a][k]
// grid(B), block(ATT)
// ---------------------------------------------------------------------------
__global__ void k_pq(const float* __restrict__ h, const float* __restrict__ Wq) {
    int b = blockIdx.x, a = threadIdx.x;
    __shared__ float sh[RNN];
    for (int k = a; k < RNN; k += ATT) sh[k] = h[b * RNN + k];
    __syncthreads();
    const float* w = Wq + (size_t)a * RNN;
    float acc = 0.f;
#pragma unroll 8
    for (int k = 0; k < RNN; k++) acc += sh[k] * w[k];
    g_pq[b * ATT + a] = acc;
}

// ---------------------------------------------------------------------------
// Kernel 2: fused location conv + projection + tanh energy
// grid(TCH, B), block(128). Per block: T-tile of 125.
//   loc[c][t] = sum_i sum_k aw[b][i][t+k-15] * cw[c][i][k]   (SAME pad, corr)
//   e[b][t]   = sum_a v[a] * tanh(pq[b][a] + pm[b][t][a] + sum_c loc[c][t]*Wl[a][c])
// ---------------------------------------------------------------------------
__global__ void k_energy(const float* __restrict__ pm, const float* __restrict__ aw,
                         const float* __restrict__ cw, const float* __restrict__ Wl,
                         const float* __restrict__ v,  const unsigned char* __restrict__ mask) {
    int b = blockIdx.y;
    int t0 = blockIdx.x * TILE;
    int tid = threadIdx.x;
    int lane = tid & 31, warp = tid >> 5;

    __shared__ float s_aw[2][TILE + 35];   // halo 15 each side (155 used)
    __shared__ float s_cw[LOC * 63];       // stride 63 (coprime w/ 32) to dodge conflicts
    __shared__ float s_loc[TILE * LOC];
    __shared__ float s_pq[ATT], s_v[ATT];
    __shared__ float s_red[TILE * 4];

    // load attention_weights_cat tile with halo (zero-padded)
    for (int j = tid; j < 2 * (TILE + 30); j += 128) {
        int i = j / (TILE + 30), jj = j - i * (TILE + 30);
        int t = t0 - 15 + jj;
        s_aw[i][jj] = (t >= 0 && t < T) ? aw[(b * 2 + i) * T + t] : 0.f;
    }
    // conv weights (32 x 2 x 31 contiguous, 62 per output channel)
    for (int j = tid; j < LOC * 2 * KS; j += 128) {
        int c = j / 62, r = j - c * 62;
        s_cw[c * 63 + r] = cw[j];
    }
    if (tid < ATT) { s_pq[tid] = g_pq[b * ATT + tid]; s_v[tid] = v[tid]; }

    // each thread owns attention dim a = tid; keep its W_loc row in registers
    float wl[LOC];
#pragma unroll
    for (int c = 0; c < LOC; c++) wl[c] = Wl[tid * LOC + c];
    __syncthreads();

    // Step 1: conv over the tile. 32*125 tasks, 62 MACs each.
    for (int idx = tid; idx < LOC * TILE; idx += 128) {
        int tt = idx >> 5, c = idx & 31;
        const float* w_ = &s_cw[c * 63];
        float acc = 0.f;
#pragma unroll
        for (int i = 0; i < 2; i++)
#pragma unroll
            for (int k = 0; k < KS; k++)
                acc += s_aw[i][tt + k] * w_[i * 31 + k];
        s_loc[tt * LOC + c] = acc;
    }
    __syncthreads();

    // Step 2: energy. thread a = tid handles ATT dim; pm reads coalesced per t.
    int a = tid;
    const float* pmb = pm + ((size_t)b * T + t0) * ATT;
    for (int tt = 0; tt < TILE; tt++) {
        float s = s_pq[a] + pmb[(size_t)tt * ATT + a];
        const float* lp = &s_loc[tt * LOC];
#pragma unroll
        for (int c = 0; c < LOC; c++) s += lp[c] * wl[c];
        float ep = s_v[a] * tanhf(s);
#pragma unroll
        for (int o = 16; o; o >>= 1) ep += __shfl_down_sync(0xffffffffu, ep, o);
        if (lane == 0) s_red[tt * 4 + warp] = ep;
    }
    __syncthreads();
    if (tid < TILE) {
        float e = s_red[tid * 4] + s_red[tid * 4 + 1] + s_red[tid * 4 + 2] + s_red[tid * 4 + 3];
        int t = t0 + tid;
        if (mask[b * T + t]) e = -INFINITY;
        g_energy[b * T + t] = e;
    }
}

// ---------------------------------------------------------------------------
// Kernel 3: softmax over T per batch, writes attention_weights to output
// grid(B), block(256)
// ---------------------------------------------------------------------------
__global__ void k_softmax(float* __restrict__ w_out) {
    int b = blockIdx.x, tid = threadIdx.x;
    __shared__ float s_e[T];
    __shared__ float red[32];

    for (int t = tid; t < T; t += 256) s_e[t] = g_energy[b * T + t];
    __syncthreads();

    float m = -INFINITY;
    for (int t = tid; t < T; t += 256) m = fmaxf(m, s_e[t]);
#pragma unroll
    for (int o = 16; o; o >>= 1) m = fmaxf(m, __shfl_xor_sync(0xffffffffu, m, o));
    if ((tid & 31) == 0) red[tid >> 5] = m;
    __syncthreads();
    if (tid < 32) {
        float mm = (tid < 8) ? red[tid] : -INFINITY;
#pragma unroll
        for (int o = 4; o; o >>= 1) mm = fmaxf(mm, __shfl_xor_sync(0xffffffffu, mm, o));
        if (tid == 0) red[0] = mm;
    }
    __syncthreads();
    m = red[0];
    __syncthreads();   // everyone read red[0] before it is reused

    float ssum = 0.f;
    for (int t = tid; t < T; t += 256) {
        float ex = __expf(s_e[t] - m);
        s_e[t] = ex;
        ssum += ex;
    }
#pragma unroll
    for (int o = 16; o; o >>= 1) ssum += __shfl_xor_sync(0xffffffffu, ssum, o);
    if ((tid & 31) == 0) red[tid >> 5] = ssum;
    __syncthreads();
    if (tid == 0) {
        float tot = 0.f;
        for (int i = 0; i < 8; i++) tot += red[i];
        red[0] = 1.f / tot;
    }
    __syncthreads();
    float inv = red[0];
    for (int t = tid; t < T; t += 256) w_out[b * T + t] = s_e[t] * inv;
}

// ---------------------------------------------------------------------------
// Kernel 4: context partial sums.  grid(TCH, B), block(EMB=512)
//   partial[b][ch][e] = sum_{t in chunk} w[b][t] * memory[b][t][e]
// ---------------------------------------------------------------------------
__global__ void k_ctx(const float* __restrict__ mem, const float* __restrict__ w) {
    int b = blockIdx.y, ch = blockIdx.x, e = threadIdx.x;
    int t0 = ch * TILE;
    const float* mp = mem + ((size_t)b * T + t0) * EMB + e;
    const float* wp = w + b * T + t0;
    float acc = 0.f;
#pragma unroll 5
    for (int tt = 0; tt < TILE; tt++)
        acc += wp[tt] * mp[(size_t)tt * EMB];
    g_partial[(b * TCH + ch) * EMB + e] = acc;
}

// Kernel 5: deterministic partial reduce. grid(B), block(EMB)
__global__ void k_reduce(float* __restrict__ out_ctx) {
    int b = blockIdx.x, e = threadIdx.x;
    float acc = 0.f;
#pragma unroll
    for (int ch = 0; ch < TCH; ch++) acc += g_partial[(b * TCH + ch) * EMB + e];
    out_ctx[b * EMB + e] = acc;
}

// ---------------------------------------------------------------------------
extern "C" void kernel_launch(void* const* d_in, const int* in_sizes, int n_in,
                              void* d_out, int out_size) {
    const float* h    = (const float*)d_in[0];   // (B, RNN)
    const float* mem  = (const float*)d_in[1];   // (B, T, EMB)
    const float* pm   = (const float*)d_in[2];   // (B, T, ATT)
    const float* aw   = (const float*)d_in[3];   // (B, 2, T)
    const unsigned char* mask = (const unsigned char*)d_in[4];  // (B, T) bool
    const float* Wq   = (const float*)d_in[5];   // (ATT, RNN)
    const float* cw   = (const float*)d_in[6];   // (LOC, 2, KS)
    const float* Wl   = (const float*)d_in[7];   // (ATT, LOC)
    const float* v    = (const float*)d_in[8];   // (1, ATT)

    float* out     = (float*)d_out;
    float* out_ctx = out;             // (B, EMB)
    float* out_w   = out + B * EMB;   // (B, T)

    k_pq<<<B, ATT>>>(h, Wq);
    dim3 g2(TCH, B);
    k_energy<<<g2, 128>>>(pm, aw, cw, Wl, v, mask);
    k_softmax<<<B, 256>>>(out_w);
    dim3 g4(TCH, B);
    k_ctx<<<g4, EMB>>>(mem, out_w);
    k_reduce<<<B, EMB>>>(out_ctx);
}

// round 2
// speedup vs baseline: 1.6992x; 1.6992x over previous
#include <cuda_runtime.h>
#include <math.h>

#define B   64
#define T   1000
#define RNN 1024
#define EMB 512
#define ATT 128
#define LOC 32
#define KS  31
#define ECH 8
#define ETILE 125  // energy tile
#define TCH 25
#define CTILE 40   // ctx tile

__device__ float g_pq[B * ATT];
__device__ float g_energy[B * T];
__device__ float g_partial[B * TCH * EMB];

__device__ __forceinline__ float fast_tanh(float x) {
    float y;
    asm("tanh.approx.f32 %0, %1;" : "=f"(y) : "f"(x));
    return y;
}

// ---------------------------------------------------------------------------
// Kernel 1: pq[b][a] = sum_k h[b][k] * Wq[a][k]
// grid(B), block(512): warp per a, lanes over k (coalesced Wq reads)
// ---------------------------------------------------------------------------
__global__ void k_pq(const float* __restrict__ h, const float* __restrict__ Wq) {
    int b = blockIdx.x, tid = threadIdx.x;
    int lane = tid & 31, warp = tid >> 5;   // 16 warps
    __shared__ float sh[RNN];
    for (int k = tid; k < RNN; k += 512) sh[k] = h[b * RNN + k];
    __syncthreads();
    for (int a = warp; a < ATT; a += 16) {
        const float* w = Wq + (size_t)a * RNN;
        float acc = 0.f;
#pragma unroll 8
        for (int k = lane; k < RNN; k += 32) acc += sh[k] * w[k];
#pragma unroll
        for (int o = 16; o; o >>= 1) acc += __shfl_down_sync(0xffffffffu, acc, o);
        if (lane == 0) g_pq[b * ATT + a] = acc;
    }
}

// ---------------------------------------------------------------------------
// Kernel 2: fused conv1d + location projection + tanh energy
// grid(ECH, B), block(128)
// ---------------------------------------------------------------------------
__global__ void k_energy(const float* __restrict__ pm, const float* __restrict__ aw,
                         const float* __restrict__ cw, const float* __restrict__ Wl,
                         const float* __restrict__ v,  const unsigned char* __restrict__ mask) {
    int b = blockIdx.y;
    int t0 = blockIdx.x * ETILE;
    int tid = threadIdx.x;
    int lane = tid & 31, warp = tid >> 5;

    __shared__ float s_aw[2][ETILE + 35];
    __shared__ float s_cw[LOC * 63];
    __shared__ float s_loc[ETILE * LOC];
    __shared__ float s_pq[ATT], s_v[ATT];
    __shared__ float s_red[ETILE * 4];

    for (int j = tid; j < 2 * (ETILE + 30); j += 128) {
        int i = j / (ETILE + 30), jj = j - i * (ETILE + 30);
        int t = t0 - 15 + jj;
        s_aw[i][jj] = (t >= 0 && t < T) ? aw[(b * 2 + i) * T + t] : 0.f;
    }
    for (int j = tid; j < LOC * 2 * KS; j += 128) {
        int c = j / 62, r = j - c * 62;
        s_cw[c * 63 + r] = cw[j];
    }
    if (tid < ATT) { s_pq[tid] = g_pq[b * ATT + tid]; s_v[tid] = v[tid]; }

    float wl[LOC];
#pragma unroll
    for (int c = 0; c < LOC; c++) wl[c] = Wl[tid * LOC + c];
    __syncthreads();

    // conv: 32 channels x 125 t, 62 MACs each
    for (int idx = tid; idx < LOC * ETILE; idx += 128) {
        int tt = idx >> 5, c = idx & 31;
        const float* w_ = &s_cw[c * 63];
        float acc = 0.f;
#pragma unroll
        for (int i = 0; i < 2; i++)
#pragma unroll
            for (int k = 0; k < KS; k++)
                acc += s_aw[i][tt + k] * w_[i * 31 + k];
        s_loc[tt * LOC + c] = acc;
    }
    __syncthreads();

    // energy: thread a = tid owns one attention dim; pm coalesced per t
    int a = tid;
    const float* pmb = pm + ((size_t)b * T + t0) * ATT + a;
    float pq_a = s_pq[a], v_a = s_v[a];
#pragma unroll 5
    for (int tt = 0; tt < ETILE; tt++) {
        float s = pq_a + pmb[(size_t)tt * ATT];
        const float* lp = &s_loc[tt * LOC];
#pragma unroll
        for (int c = 0; c < LOC; c++) s += lp[c] * wl[c];
        float ep = v_a * fast_tanh(s);
#pragma unroll
        for (int o = 16; o; o >>= 1) ep += __shfl_down_sync(0xffffffffu, ep, o);
        if (lane == 0) s_red[tt * 4 + warp] = ep;
    }
    __syncthreads();
    if (tid < ETILE) {
        float e = s_red[tid * 4] + s_red[tid * 4 + 1] + s_red[tid * 4 + 2] + s_red[tid * 4 + 3];
        int t = t0 + tid;
        if (mask[b * T + t]) e = -INFINITY;
        g_energy[b * T + t] = e;
    }
}

// ---------------------------------------------------------------------------
// Kernel 3: softmax over T, writes attention weights to output
// ---------------------------------------------------------------------------
__global__ void k_softmax(float* __restrict__ w_out) {
    int b = blockIdx.x, tid = threadIdx.x;
    __shared__ float s_e[T];
    __shared__ float red[32];

    for (int t = tid; t < T; t += 256) s_e[t] = g_energy[b * T + t];
    __syncthreads();

    float m = -INFINITY;
    for (int t = tid; t < T; t += 256) m = fmaxf(m, s_e[t]);
#pragma unroll
    for (int o = 16; o; o >>= 1) m = fmaxf(m, __shfl_xor_sync(0xffffffffu, m, o));
    if ((tid & 31) == 0) red[tid >> 5] = m;
    __syncthreads();
    if (tid < 32) {
        float mm = (tid < 8) ? red[tid] : -INFINITY;
#pragma unroll
        for (int o = 4; o; o >>= 1) mm = fmaxf(mm, __shfl_xor_sync(0xffffffffu, mm, o));
        if (tid == 0) red[0] = mm;
    }
    __syncthreads();
    m = red[0];
    __syncthreads();

    float ssum = 0.f;
    for (int t = tid; t < T; t += 256) {
        float ex = __expf(s_e[t] - m);
        s_e[t] = ex;
        ssum += ex;
    }
#pragma unroll
    for (int o = 16; o; o >>= 1) ssum += __shfl_xor_sync(0xffffffffu, ssum, o);
    if ((tid & 31) == 0) red[tid >> 5] = ssum;
    __syncthreads();
    if (tid == 0) {
        float tot = 0.f;
        for (int i = 0; i < 8; i++) tot += red[i];
        red[0] = 1.f / tot;
    }
    __syncthreads();
    float inv = red[0];
    for (int t = tid; t < T; t += 256) w_out[b * T + t] = s_e[t] * inv;
}

// ---------------------------------------------------------------------------
// Kernel 4: context partials. grid(TCH, B), block(128), float4 loads
// ---------------------------------------------------------------------------
__global__ void k_ctx(const float4* __restrict__ mem, const float* __restrict__ w) {
    int b = blockIdx.y, ch = blockIdx.x, e4 = threadIdx.x;  // 0..127
    int t0 = ch * CTILE;
    __shared__ float sw[CTILE];
    if (threadIdx.x < CTILE) sw[threadIdx.x] = w[b * T + t0 + threadIdx.x];
    __syncthreads();
    const float4* mp = mem + ((size_t)b * T + t0) * (EMB / 4) + e4;
    float ax = 0.f, ay = 0.f, az = 0.f, aw_ = 0.f;
#pragma unroll 8
    for (int tt = 0; tt < CTILE; tt++) {
        float4 m = mp[(size_t)tt * (EMB / 4)];
        float wv = sw[tt];
        ax += wv * m.x; ay += wv * m.y; az += wv * m.z; aw_ += wv * m.w;
    }
    float4 r; r.x = ax; r.y = ay; r.z = az; r.w = aw_;
    ((float4*)g_partial)[(b * TCH + ch) * (EMB / 4) + e4] = r;
}

// Kernel 5: deterministic reduce of partials. grid(B), block(EMB)
__global__ void k_reduce(float* __restrict__ out_ctx) {
    int b = blockIdx.x, e = threadIdx.x;
    float acc = 0.f;
#pragma unroll
    for (int ch = 0; ch < TCH; ch++) acc += g_partial[(b * TCH + ch) * EMB + e];
    out_ctx[b * EMB + e] = acc;
}

// ---------------------------------------------------------------------------
extern "C" void kernel_launch(void* const* d_in, const int* in_sizes, int n_in,
                              void* d_out, int out_size) {
    const float* h    = (const float*)d_in[0];   // (B, RNN)
    const float* mem  = (const float*)d_in[1];   // (B, T, EMB)
    const float* pm   = (const float*)d_in[2];   // (B, T, ATT)
    const float* aw   = (const float*)d_in[3];   // (B, 2, T)
    const unsigned char* mask = (const unsigned char*)d_in[4];
    const float* Wq   = (const float*)d_in[5];   // (ATT, RNN)
    const float* cw   = (const float*)d_in[6];   // (LOC, 2, KS)
    const float* Wl   = (const float*)d_in[7];   // (ATT, LOC)
    const float* v    = (const float*)d_in[8];   // (1, ATT)

    float* out     = (float*)d_out;
    float* out_ctx = out;             // (B, EMB)
    float* out_w   = out + B * EMB;   // (B, T)

    k_pq<<<B, 512>>>(h, Wq);
    dim3 g2(ECH, B);
    k_energy<<<g2, 128>>>(pm, aw, cw, Wl, v, mask);
    k_softmax<<<B, 256>>>(out_w);
    dim3 g4(TCH, B);
    k_ctx<<<g4, 128>>>((const float4*)mem, out_w);
    k_reduce<<<B, EMB>>>(out_ctx);
}

// round 3
// speedup vs baseline: 2.5157x; 1.4806x over previous
#include <cuda_runtime.h>
#include <math.h>

#define B   64
#define T   1000
#define RNN 1024
#define EMB 512
#define ATT 128
#define LOC 32
#define KS  31
#define ECH 10
#define ETILE 100
#define TCH 25
#define CTILE 40

__device__ float g_pq[B * ATT];
__device__ float g_energy[B * T];
__device__ float g_partial[B * TCH * EMB];

__device__ __forceinline__ float fast_tanh(float x) {
    float y;
    asm("tanh.approx.f32 %0, %1;" : "=f"(y) : "f"(x));
    return y;
}
__device__ __forceinline__ unsigned long long fma2(unsigned long long a,
                                                   unsigned long long b,
                                                   unsigned long long c) {
    unsigned long long d;
    asm("fma.rn.f32x2 %0, %1, %2, %3;" : "=l"(d) : "l"(a), "l"(b), "l"(c));
    return d;
}
__device__ __forceinline__ unsigned long long pack2(float lo, float hi) {
    unsigned long long r;
    asm("mov.b64 %0, {%1, %2};" : "=l"(r) : "f"(lo), "f"(hi));
    return r;
}
__device__ __forceinline__ float sum2(unsigned long long p) {
    float lo, hi;
    asm("mov.b64 {%0, %1}, %2;" : "=f"(lo), "=f"(hi) : "l"(p));
    return lo + hi;
}

// ---------------------------------------------------------------------------
// Kernel 1: pq[b][a] = sum_k h[b][k]*Wq[a][k].  grid(B), block(1024)
// ---------------------------------------------------------------------------
__global__ void k_pq(const float* __restrict__ h, const float* __restrict__ Wq) {
    int b = blockIdx.x, tid = threadIdx.x;
    int lane = tid & 31, warp = tid >> 5;   // 32 warps
    __shared__ float sh[RNN];
    for (int k = tid; k < RNN; k += 1024) sh[k] = h[b * RNN + k];
    __syncthreads();
#pragma unroll
    for (int aa = 0; aa < 4; aa++) {
        int a = warp + aa * 32;
        const float* w = Wq + (size_t)a * RNN;
        float acc = 0.f;
#pragma unroll 8
        for (int k = lane; k < RNN; k += 32) acc += sh[k] * w[k];
#pragma unroll
        for (int o = 16; o; o >>= 1) acc += __shfl_down_sync(0xffffffffu, acc, o);
        if (lane == 0) g_pq[b * ATT + a] = acc;
    }
}

// ---------------------------------------------------------------------------
// Kernel 2: fused conv1d + location projection + tanh energy
// grid(ECH, B), block(128)
// ---------------------------------------------------------------------------
__global__ void __launch_bounds__(128) k_energy(
        const float* __restrict__ pm, const float* __restrict__ aw,
        const float* __restrict__ cw, const float* __restrict__ Wl,
        const float* __restrict__ v,  const unsigned char* __restrict__ mask) {
    int b = blockIdx.y;
    int t0 = blockIdx.x * ETILE;
    int tid = threadIdx.x;
    int lane = tid & 31, warp = tid >> 5;

    __shared__ __align__(16) unsigned long long s_aw2[ETILE + 32]; // (ch0,ch1) pairs, halo 15
    __shared__ __align__(16) float s_loc[ETILE * LOC];             // [t][c], 128B rows
    __shared__ float s_pq[ATT], s_v[ATT];
    __shared__ float s_red[ETILE * 4];

    // load aw window as channel pairs
    for (int j = tid; j < ETILE + 30; j += 128) {
        int t = t0 - 15 + j;
        float c0 = 0.f, c1 = 0.f;
        if (t >= 0 && t < T) {
            c0 = aw[(size_t)b * 2 * T + t];
            c1 = aw[(size_t)(b * 2 + 1) * T + t];
        }
        s_aw2[j] = pack2(c0, c1);
    }
    if (tid < ATT) { s_pq[tid] = g_pq[b * ATT + tid]; s_v[tid] = v[tid]; }

    // conv weights for this thread's channel (c fixed = tid&31), packed over i
    int c = tid & 31;
    unsigned long long cw2[KS];
#pragma unroll
    for (int k = 0; k < KS; k++)
        cw2[k] = pack2(cw[c * 62 + k], cw[c * 62 + 31 + k]);
    __syncthreads();

    // conv: 32 ch x ETILE t; thread handles fixed c, strided tt
    for (int idx = tid; idx < LOC * ETILE; idx += 128) {
        int tt = idx >> 5;
        unsigned long long acc2 = 0ull;   // (0.f, 0.f)
#pragma unroll
        for (int k = 0; k < KS; k++)
            acc2 = fma2(s_aw2[tt + k], cw2[k], acc2);
        s_loc[tt * LOC + c] = sum2(acc2);
    }

    // Wl row for a = tid, packed over c-pairs
    int a = tid;
    unsigned long long wl2[LOC / 2];
#pragma unroll
    for (int j = 0; j < LOC / 2; j++)
        wl2[j] = pack2(Wl[a * LOC + 2 * j], Wl[a * LOC + 2 * j + 1]);
    float pq_a = 0.f, v_a = 0.f;
    __syncthreads();
    pq_a = s_pq[a]; v_a = s_v[a];

    const float* pmb = pm + ((size_t)b * T + t0) * ATT + a;
#pragma unroll 2
    for (int tt = 0; tt < ETILE; tt += 2) {
        float pm0 = pmb[(size_t)tt * ATT];
        float pm1 = pmb[(size_t)(tt + 1) * ATT];
        const unsigned long long* l0 = (const unsigned long long*)&s_loc[tt * LOC];
        const unsigned long long* l1 = (const unsigned long long*)&s_loc[(tt + 1) * LOC];
        unsigned long long a0 = 0ull, a1 = 0ull;
#pragma unroll
        for (int j = 0; j < LOC / 2; j++) {
            a0 = fma2(l0[j], wl2[j], a0);
            a1 = fma2(l1[j], wl2[j], a1);
        }
        float e0 = v_a * fast_tanh(pq_a + pm0 + sum2(a0));
        float e1 = v_a * fast_tanh(pq_a + pm1 + sum2(a1));
#pragma unroll
        for (int o = 16; o; o >>= 1) {
            e0 += __shfl_down_sync(0xffffffffu, e0, o);
            e1 += __shfl_down_sync(0xffffffffu, e1, o);
        }
        if (lane == 0) {
            s_red[tt * 4 + warp] = e0;
            s_red[(tt + 1) * 4 + warp] = e1;
        }
    }
    __syncthreads();
    if (tid < ETILE) {
        float e = s_red[tid * 4] + s_red[tid * 4 + 1] + s_red[tid * 4 + 2] + s_red[tid * 4 + 3];
        int t = t0 + tid;
        if (mask[b * T + t]) e = -INFINITY;
        g_energy[b * T + t] = e;
    }
}

// ---------------------------------------------------------------------------
// Kernel 3: softmax over T per batch.  grid(B), block(1024)
// ---------------------------------------------------------------------------
__global__ void k_softmax(float* __restrict__ w_out) {
    int b = blockIdx.x, tid = threadIdx.x;
    __shared__ float s_e[T];
    __shared__ float red[32];

    float ev = (tid < T) ? g_energy[b * T + tid] : -INFINITY;
    if (tid < T) s_e[tid] = ev;

    float m = ev;
#pragma unroll
    for (int o = 16; o; o >>= 1) m = fmaxf(m, __shfl_xor_sync(0xffffffffu, m, o));
    if ((tid & 31) == 0) red[tid >> 5] = m;
    __syncthreads();
    if (tid < 32) {
        float mm = red[tid];
#pragma unroll
        for (int o = 16; o; o >>= 1) mm = fmaxf(mm, __shfl_xor_sync(0xffffffffu, mm, o));
        if (tid == 0) red[0] = mm;
    }
    __syncthreads();
    m = red[0];
    __syncthreads();

    float ex = (tid < T) ? __expf(ev - m) : 0.f;
    float s = ex;
#pragma unroll
    for (int o = 16; o; o >>= 1) s += __shfl_xor_sync(0xffffffffu, s, o);
    if ((tid & 31) == 0) red[tid >> 5] = s;
    __syncthreads();
    if (tid < 32) {
        float ss = red[tid];
#pragma unroll
        for (int o = 16; o; o >>= 1) ss += __shfl_xor_sync(0xffffffffu, ss, o);
        if (tid == 0) red[0] = 1.f / ss;
    }
    __syncthreads();
    float inv = red[0];
    if (tid < T) w_out[b * T + tid] = ex * inv;
}

// ---------------------------------------------------------------------------
// Kernel 4: context partials. grid(TCH, B), block(128), streaming float4
// ---------------------------------------------------------------------------
__global__ void k_ctx(const float4* __restrict__ mem, const float* __restrict__ w) {
    int b = blockIdx.y, ch = blockIdx.x, e4 = threadIdx.x;
    int t0 = ch * CTILE;
    __shared__ float sw[CTILE];
    if (threadIdx.x < CTILE) sw[threadIdx.x] = w[b * T + t0 + threadIdx.x];
    __syncthreads();
    const float4* mp = mem + ((size_t)b * T + t0) * (EMB / 4) + e4;
    float ax = 0.f, ay = 0.f, az = 0.f, aww = 0.f;
#pragma unroll 10
    for (int tt = 0; tt < CTILE; tt++) {
        float4 m = __ldcs(mp + (size_t)tt * (EMB / 4));
        float wv = sw[tt];
        ax += wv * m.x; ay += wv * m.y; az += wv * m.z; aww += wv * m.w;
    }
    float4 r; r.x = ax; r.y = ay; r.z = az; r.w = aww;
    ((float4*)g_partial)[(b * TCH + ch) * (EMB / 4) + e4] = r;
}

// Kernel 5: deterministic reduce. grid(B), block(EMB)
__global__ void k_reduce(float* __restrict__ out_ctx) {
    int b = blockIdx.x, e = threadIdx.x;
    float acc = 0.f;
#pragma unroll
    for (int ch = 0; ch < TCH; ch++) acc += g_partial[(b * TCH + ch) * EMB + e];
    out_ctx[b * EMB + e] = acc;
}

// ---------------------------------------------------------------------------
extern "C" void kernel_launch(void* const* d_in, const int* in_sizes, int n_in,
                              void* d_out, int out_size) {
    const float* h    = (const float*)d_in[0];
    const float* mem  = (const float*)d_in[1];
    const float* pm   = (const float*)d_in[2];
    const float* aw   = (const float*)d_in[3];
    const unsigned char* mask = (const unsigned char*)d_in[4];
    const float* Wq   = (const float*)d_in[5];
    const float* cw   = (const float*)d_in[6];
    const float* Wl   = (const float*)d_in[7];
    const float* v    = (const float*)d_in[8];

    float* out     = (float*)d_out;
    float* out_ctx = out;             // (B, EMB)
    float* out_w   = out + B * EMB;   // (B, T)

    k_pq<<<B, 1024>>>(h, Wq);
    dim3 g2(ECH, B);
    k_energy<<<g2, 128>>>(pm, aw, cw, Wl, v, mask);
    k_softmax<<<B, 1024>>>(out_w);
    dim3 g4(TCH, B);
    k_ctx<<<g4, 128>>>((const float4*)mem, out_w);
    k_reduce<<<B, EMB>>>(out_ctx);
}